// round 1
// baseline (speedup 1.0000x reference)
#include <cuda_runtime.h>
#include <cuda_bf16.h>
#include <cstdint>

#define NN 100000
#define EE 1600000
#define FF 128
#define RR 50
#define BN_EPS 1e-3f

// Scratch (allocation-free rule: device globals)
__device__ float g_h[(size_t)NN * FF];    // batchnormed features
__device__ float g_pre[(size_t)NN * FF];  // h*(coeff+1), accumulated by SpMM

// ---------------------------------------------------------------------------
// Kernel 1: BatchNorm (inference) + initialize pre = h * (coeff + 1)
// One thread per float4 (4 features). N*F/4 = 3.2M threads.
// ---------------------------------------------------------------------------
__global__ void bn_kernel(const float* __restrict__ x,
                          const float* __restrict__ coeff,
                          const float* __restrict__ gamma,
                          const float* __restrict__ beta,
                          const float* __restrict__ mean,
                          const float* __restrict__ var)
{
    int idx = blockIdx.x * blockDim.x + threadIdx.x;
    if (idx >= NN * (FF / 4)) return;
    int row = idx >> 5;          // FF/4 == 32 float4 per row
    int c   = (idx & 31) * 4;    // feature column base

    float4 xv = ((const float4*)x)[idx];

    float s0 = gamma[c + 0] * rsqrtf(var[c + 0] + BN_EPS);
    float s1 = gamma[c + 1] * rsqrtf(var[c + 1] + BN_EPS);
    float s2 = gamma[c + 2] * rsqrtf(var[c + 2] + BN_EPS);
    float s3 = gamma[c + 3] * rsqrtf(var[c + 3] + BN_EPS);

    float4 hv;
    hv.x = (xv.x - mean[c + 0]) * s0 + beta[c + 0];
    hv.y = (xv.y - mean[c + 1]) * s1 + beta[c + 1];
    hv.z = (xv.z - mean[c + 2]) * s2 + beta[c + 2];
    hv.w = (xv.w - mean[c + 3]) * s3 + beta[c + 3];

    ((float4*)g_h)[idx] = hv;

    float cm = coeff[row] + 1.0f;
    float4 pv = make_float4(hv.x * cm, hv.y * cm, hv.z * cm, hv.w * cm);
    ((float4*)g_pre)[idx] = pv;
}

// ---------------------------------------------------------------------------
// Kernel 2: SpMM scatter.  pre[row] += w_e * h[col]  via red.global.add.v4.f32
// One warp processes 32 edges: lane e owns edge metadata, broadcast via shfl;
// all 32 lanes cooperatively move the 128-float row (float4 per lane).
// ---------------------------------------------------------------------------
__global__ void spmm_kernel(const int*   __restrict__ rows,
                            const int*   __restrict__ cols,
                            const float* __restrict__ vals,
                            const int*   __restrict__ rels,
                            const float* __restrict__ rc)
{
    int lane = threadIdx.x & 31;
    int warp = blockIdx.x * (blockDim.x >> 5) + (threadIdx.x >> 5);
    long base = (long)warp * 32;
    if (base >= EE) return;

    long e = base + lane;
    int r = 0, c = 0;
    float w = 0.0f;
    if (e < EE) {
        r = rows[e];
        c = cols[e];
        w = vals[e] / (rc[rels[e]] + 1.0f);
    }
    int cnt = (int)min((long)32, (long)EE - base);

    for (int i = 0; i < cnt; i++) {
        int   ce = __shfl_sync(0xffffffffu, c, i);
        int   re = __shfl_sync(0xffffffffu, r, i);
        float we = __shfl_sync(0xffffffffu, w, i);

        float4 hv = __ldg(((const float4*)(g_h + (size_t)ce * FF)) + lane);
        float mx = we * hv.x, my = we * hv.y, mz = we * hv.z, mw = we * hv.w;

        float* dst = g_pre + (size_t)re * FF + lane * 4;
        asm volatile("red.global.add.v4.f32 [%0], {%1, %2, %3, %4};"
                     :: "l"(dst), "f"(mx), "f"(my), "f"(mz), "f"(mw)
                     : "memory");
    }
}

// ---------------------------------------------------------------------------
// Kernel 3: out = pre @ W + bias, packed-f32x2 FFMA.
// Block: 256 threads, tile 128 rows x 128 cols. Thread tile 8x8.
// W (64KB) + As (66KB, stride 132 to avoid bank conflicts) in dynamic SMEM.
// ---------------------------------------------------------------------------
#define AS_STRIDE 132

__global__ void __launch_bounds__(256)
gemm_kernel(const float* __restrict__ W,
            const float* __restrict__ bias,
            float* __restrict__ out)
{
    extern __shared__ float sm[];
    float* Ws = sm;                 // [128][128]
    float* As = sm + FF * FF;       // [128][AS_STRIDE]

    int tid  = threadIdx.x;
    int row0 = blockIdx.x * 128;

    // Load W into SMEM (256 threads x 16 float4)
    for (int i = tid; i < FF * FF / 4; i += 256)
        ((float4*)Ws)[i] = ((const float4*)W)[i];

    // Load pre tile (guard tail rows with zeros)
    for (int i = tid; i < 128 * (FF / 4); i += 256) {
        int lr = i >> 5;         // local row
        int c4 = i & 31;         // float4 column
        int gr = row0 + lr;
        float4 v = make_float4(0.f, 0.f, 0.f, 0.f);
        if (gr < NN) v = ((const float4*)g_pre)[(size_t)gr * 32 + c4];
        ((float4*)(As + lr * AS_STRIDE))[c4] = v;
    }
    __syncthreads();

    int rg = tid >> 4;           // 0..15 row groups
    int cg = tid & 15;           // 0..15 col groups
    int rbase = rg * 8;
    int cbase = cg * 8;

    unsigned long long acc[8][4];
#pragma unroll
    for (int i = 0; i < 8; i++)
#pragma unroll
        for (int j = 0; j < 4; j++)
            acc[i][j] = 0ull;    // (0.0f, 0.0f)

#pragma unroll 4
    for (int k = 0; k < FF; k++) {
        const float* wrow = Ws + k * FF + cbase;
        ulonglong2 b01 = *(const ulonglong2*)(wrow);
        ulonglong2 b23 = *(const ulonglong2*)(wrow + 4);
        unsigned long long bb0 = b01.x, bb1 = b01.y, bb2 = b23.x, bb3 = b23.y;

#pragma unroll
        for (int i = 0; i < 8; i++) {
            float a = As[(rbase + i) * AS_STRIDE + k];
            unsigned long long ap;
            asm("mov.b64 %0, {%1, %1};" : "=l"(ap) : "r"(__float_as_uint(a)));
            asm("fma.rn.f32x2 %0, %1, %2, %0;" : "+l"(acc[i][0]) : "l"(ap), "l"(bb0));
            asm("fma.rn.f32x2 %0, %1, %2, %0;" : "+l"(acc[i][1]) : "l"(ap), "l"(bb1));
            asm("fma.rn.f32x2 %0, %1, %2, %0;" : "+l"(acc[i][2]) : "l"(ap), "l"(bb2));
            asm("fma.rn.f32x2 %0, %1, %2, %0;" : "+l"(acc[i][3]) : "l"(ap), "l"(bb3));
        }
    }

    // Epilogue: bias add + store (float2 per pair)
    float bv[8];
#pragma unroll
    for (int j = 0; j < 8; j++) bv[j] = bias[cbase + j];

#pragma unroll
    for (int i = 0; i < 8; i++) {
        int row = row0 + rbase + i;
        if (row >= NN) break;
        float* orow = out + (size_t)row * FF + cbase;
#pragma unroll
        for (int j = 0; j < 4; j++) {
            unsigned int lo, hi;
            asm("mov.b64 {%0, %1}, %2;" : "=r"(lo), "=r"(hi) : "l"(acc[i][j]));
            float2 v;
            v.x = __uint_as_float(lo) + bv[2 * j + 0];
            v.y = __uint_as_float(hi) + bv[2 * j + 1];
            *(float2*)(orow + 2 * j) = v;
        }
    }
}

// ---------------------------------------------------------------------------
extern "C" void kernel_launch(void* const* d_in, const int* in_sizes, int n_in,
                              void* d_out, int out_size)
{
    const float* x          = (const float*)d_in[0];
    const int*   edge_rows  = (const int*)  d_in[1];
    const int*   edge_cols  = (const int*)  d_in[2];
    const float* edge_vals  = (const float*)d_in[3];
    const int*   rel_ids    = (const int*)  d_in[4];
    const float* rel_coeffs = (const float*)d_in[5];
    const float* coeff_k    = (const float*)d_in[6];
    const float* dense_W    = (const float*)d_in[7];
    const float* dense_b    = (const float*)d_in[8];
    const float* bn_gamma   = (const float*)d_in[9];
    const float* bn_beta    = (const float*)d_in[10];
    const float* bn_mean    = (const float*)d_in[11];
    const float* bn_var     = (const float*)d_in[12];
    float*       out        = (float*)d_out;

    // 1) BN + pre-init
    {
        int total = NN * (FF / 4);
        int threads = 256;
        int blocks = (total + threads - 1) / threads;
        bn_kernel<<<blocks, threads>>>(x, coeff_k, bn_gamma, bn_beta, bn_mean, bn_var);
    }

    // 2) SpMM scatter with vector reductions
    {
        int threads = 256;                       // 8 warps -> 256 edges/block
        int blocks = (EE + threads - 1) / threads;
        spmm_kernel<<<blocks, threads>>>(edge_rows, edge_cols, edge_vals,
                                         rel_ids, rel_coeffs);
    }

    // 3) Dense GEMM
    {
        int smem = (FF * FF + 128 * AS_STRIDE) * sizeof(float);  // ~131.6 KB
        cudaFuncSetAttribute(gemm_kernel,
                             cudaFuncAttributeMaxDynamicSharedMemorySize, smem);
        int blocks = (NN + 127) / 128;
        gemm_kernel<<<blocks, 256, smem>>>(dense_W, dense_b, out);
    }
}